// round 16
// baseline (speedup 1.0000x reference)
#include <cuda_runtime.h>

// ---------------------------------------------------------------------------
// MemoryAugmented: value[b,t,n,d] = softmax_m( sum_{l,d'} x[b,l,n,d'] M[t,m,d'] ) @ M[t]
// Key identity: l-sum is independent of t -> xs[b,n,:] = sum_l x[b,l,n,:]
// One fused kernel: thread = row (b,n); xs kept in packed f32x2 registers,
// reused across all 12 t. M[t] staged in smem, scores staged in smem
// (conflict-free [m][tid]) so m-loops stay rolled (no local-mem spills,
// small I-cache footprint). All math fp32 (fma.rn.f32x2 packed, 2x FFMA rate).
// ---------------------------------------------------------------------------

#define FFMA2(d, a, b) asm("fma.rn.f32x2 %0, %1, %2, %0;" : "+l"(d) : "l"(a), "l"(b))
#define MUL2(d, a, b)  asm("mul.rn.f32x2 %0, %1, %2;" : "=l"(d) : "l"(a), "l"(b))
#define PACK2(d, lo, hi) asm("mov.b64 %0, {%1, %2};" : "=l"(d) : "f"(lo), "f"(hi))
#define UNPACK2(lo, hi, s) asm("mov.b64 {%0, %1}, %2;" : "=f"(lo), "=f"(hi) : "l"(s))

namespace {
constexpr int kB = 64;
constexpr int kL = 12;
constexpr int kN = 883;
constexpr int kD = 64;
constexpr int kT = 12;
constexpr int kM = 64;
constexpr int kRows = kB * kN;        // 56512
constexpr int kTPB  = 128;
constexpr int kBlocks = (kRows + kTPB - 1) / kTPB;  // 442
// smem: M tile (64*64 f32 = 16KB) + score staging (64 * kTPB f32 = 32KB) = 48KB
constexpr int kSmemFloats = kM * kD + kM * kTPB;
}  // namespace

extern __shared__ float smem[];

__global__ __launch_bounds__(kTPB, 2)
void ma_fused_kernel(const float* __restrict__ x,
                     const float* __restrict__ Mg,
                     float* __restrict__ out) {
    float* sM = smem;                 // [64][64]  M[t] tile
    float* sS = smem + kM * kD;       // [64][kTPB] per-thread score column

    const int tid = threadIdx.x;
    const int r   = blockIdx.x * kTPB + tid;
    const bool valid = (r < kRows);
    const int b = r / kN;
    const int n = r % kN;

    // ---------------- Phase 0: xs[b,n,:] = sum_l x[b,l,n,:]  ----------------
    // Held as 32 packed f32x2 registers for the whole kernel.
    unsigned long long xs2[32];
    if (valid) {
        const float4* xp = reinterpret_cast<const float4*>(x);
        const int base = (b * kL * kN + n) * (kD / 4);   // float4 units
        float4 acc[16];
#pragma unroll
        for (int j = 0; j < 16; j++) acc[j] = xp[base + j];
#pragma unroll 1
        for (int l = 1; l < kL; l++) {
            const int o = base + l * kN * (kD / 4);
#pragma unroll
            for (int j = 0; j < 16; j++) {
                float4 v = xp[o + j];
                acc[j].x += v.x; acc[j].y += v.y;
                acc[j].z += v.z; acc[j].w += v.w;
            }
        }
#pragma unroll
        for (int j = 0; j < 16; j++) {
            PACK2(xs2[2 * j + 0], acc[j].x, acc[j].y);
            PACK2(xs2[2 * j + 1], acc[j].z, acc[j].w);
        }
    }

    // ---------------- Phase 1: loop over t ----------------
#pragma unroll 1
    for (int t = 0; t < kT; t++) {
        __syncthreads();   // protect sM of previous iteration
        {
            // cooperative coalesced load of M[t]: 4096 floats = 1024 float4
            const float4* mg4 = reinterpret_cast<const float4*>(Mg + t * kM * kD);
            float4* sM4 = reinterpret_cast<float4*>(sM);
#pragma unroll
            for (int k = 0; k < 8; k++)
                sM4[tid + k * kTPB] = mg4[tid + k * kTPB];
        }
        __syncthreads();

        if (valid) {
            const ulonglong2* m2 = reinterpret_cast<const ulonglong2*>(sM);

            // ---- scores: s[m] = xs . M[t][m][:] ----
            float mx = -1e30f;
#pragma unroll 4
            for (int m = 0; m < kM; m++) {
                unsigned long long a0 = 0ull, a1 = 0ull;   // == (0.f,0.f)
                const ulonglong2* row = m2 + m * 16;
#pragma unroll
                for (int j = 0; j < 16; j++) {
                    ulonglong2 q = row[j];
                    FFMA2(a0, xs2[2 * j + 0], q.x);
                    FFMA2(a1, xs2[2 * j + 1], q.y);
                }
                float l0, h0, l1, h1;
                UNPACK2(l0, h0, a0);
                UNPACK2(l1, h1, a1);
                float s = (l0 + h0) + (l1 + h1);
                sS[m * kTPB + tid] = s;
                mx = fmaxf(mx, s);
            }

            // ---- fused softmax + value accumulation ----
            unsigned long long o2[32];
#pragma unroll
            for (int j = 0; j < 32; j++) o2[j] = 0ull;
            float sum = 0.f;
#pragma unroll 2
            for (int m = 0; m < kM; m++) {
                float e = __expf(sS[m * kTPB + tid] - mx);
                sum += e;
                unsigned long long pm2;
                PACK2(pm2, e, e);
                const ulonglong2* row = m2 + m * 16;
#pragma unroll
                for (int j = 0; j < 16; j++) {
                    ulonglong2 q = row[j];
                    FFMA2(o2[2 * j + 0], pm2, q.x);
                    FFMA2(o2[2 * j + 1], pm2, q.y);
                }
            }

            // ---- epilogue: scale by 1/sum, store ----
            const float inv = 1.0f / sum;
            unsigned long long inv2;
            PACK2(inv2, inv, inv);
            float4* op = reinterpret_cast<float4*>(out) +
                         ((b * kT + t) * kN + n) * (kD / 4);
#pragma unroll
            for (int j = 0; j < 16; j++) {
                unsigned long long r0 = o2[2 * j + 0], r1 = o2[2 * j + 1];
                MUL2(r0, r0, inv2);
                MUL2(r1, r1, inv2);
                float4 v;
                UNPACK2(v.x, v.y, r0);
                UNPACK2(v.z, v.w, r1);
                op[j] = v;
            }
        }
    }
}

extern "C" void kernel_launch(void* const* d_in, const int* in_sizes, int n_in,
                              void* d_out, int out_size) {
    const float* x  = reinterpret_cast<const float*>(d_in[0]);
    const float* Mg = reinterpret_cast<const float*>(d_in[1]);
    // defensive: x is the big tensor (43.4M elems), M is 49152
    if (n_in >= 2 && in_sizes[0] < in_sizes[1]) {
        const float* tmp = x; x = Mg; Mg = tmp;
    }
    float* out = reinterpret_cast<float*>(d_out);

    const size_t smem_bytes = kSmemFloats * sizeof(float);  // 49152 = 48KB (default limit)
    ma_fused_kernel<<<kBlocks, kTPB, smem_bytes>>>(x, Mg, out);
}